// round 2
// baseline (speedup 1.0000x reference)
#include <cuda_runtime.h>
#include <math.h>

// ---------------- problem constants ----------------
#define BB 4
#define HH 256
#define WW 256
#define CC 32
#define NPIX (HH*WW)            // 65536
#define IMG_ELEMS (BB*NPIX*CC)  // 8388608

// ---------------- device scratch (no allocs allowed) ----------------
__device__ float g_part[BB*256*1056];   // per-block partials: 1024 cov + 32 hsi sums
__device__ float g_M[BB*1024];          // fused proj @ blockdiag(attn), per batch
__device__ float g_cmask[BB*CC];        // channel mask, pixel-free
__device__ float g_smask[BB*NPIX];      // spatial mask in pixel (h,w) order
__device__ float g_kcomb[49*32];        // folded 7x7(+3x3 center) -> 1ch kernel
__device__ float g_vg[IMG_ELEMS];       // gated V (NHWC)
__device__ float g_vspec[IMG_ELEMS];    // v_spec (NHWC)
__device__ float g_tpos[IMG_ELEMS];     // gelu(conv(v_spec)+b1) (NHWC)
__device__ float g_outn[IMG_ELEMS];     // out1+pos in NHWC before final transpose

__device__ __forceinline__ float gelu_exact(float x) {
    return 0.5f * x * (1.0f + erff(x * 0.70710678118654752f));
}
__device__ __forceinline__ float sigmoidf_(float x) {
    return 1.0f / (1.0f + expf(-x));
}

// ---------------- 0) fold spatial-attention kernels ----------------
// kcomb[t][i], t=(ty+3)*7+(tx+3): c3[1]*sum_o c2b[o]*c2a[o,i,tx+3,ty+3]
//                                + (center 3x3) c3[0]*sum_o c1b[o]*c1a[o,i,tx+1,ty+1]
__global__ void prep_k(const float* __restrict__ c1a, const float* __restrict__ c1b,
                       const float* __restrict__ c2a, const float* __restrict__ c2b,
                       const float* __restrict__ c3) {
    int tid = threadIdx.x;
    float w3 = c3[0], w7 = c3[1];
    for (int e = tid; e < 49*32; e += 256) {
        int t = e >> 5, i = e & 31;
        int ty = t / 7 - 3, tx = t % 7 - 3;
        float s = 0.f;
        for (int o = 0; o < 32; o++)
            s += c2b[o] * c2a[((o*32 + i)*7 + (tx+3))*7 + (ty+3)];
        s *= w7;
        if (tx >= -1 && tx <= 1 && ty >= -1 && ty <= 1) {
            float s1 = 0.f;
            for (int o = 0; o < 32; o++)
                s1 += c1b[o] * c1a[((o*32 + i)*3 + (tx+1))*3 + (ty+1)];
            s += w3 * s1;
        }
        g_kcomb[e] = s;
    }
}

// ---------------- 1) stats stage 1: per-chunk cov(x_fu) + channel sums(x_hsi) ----------------
__global__ __launch_bounds__(256) void stats1_k(const float* __restrict__ xfu,
                                                const float* __restrict__ xhsi) {
    __shared__ float sx[256*32];
    __shared__ float sh[8][32];
    int b = blockIdx.y, blk = blockIdx.x, tid = threadIdx.x;
    size_t base = ((size_t)b*NPIX + (size_t)blk*256) * 32;
    for (int k = 0; k < 32; k++) sx[k*256 + tid] = xfu[base + (size_t)k*256 + tid];
    // x_hsi channel sums (32 pixels per thread-group)
    {
        int c = tid & 31, grp = tid >> 5;
        float s = 0.f;
        for (int p = grp; p < 256; p += 8) s += xhsi[base + (size_t)p*32 + c];
        sh[grp][c] = s;
    }
    __syncthreads();
    // cov: 4 entries per thread
    int e0 = tid * 4;
    int i = e0 >> 5, j0 = e0 & 31;
    float4 a = make_float4(0.f, 0.f, 0.f, 0.f);
    const float4* sx4 = (const float4*)sx;
    for (int p = 0; p < 256; p++) {
        float xi = sx[p*32 + i];
        float4 xj = sx4[p*8 + (j0 >> 2)];
        a.x += xi * xj.x; a.y += xi * xj.y; a.z += xi * xj.z; a.w += xi * xj.w;
    }
    float* part = &g_part[((size_t)b*256 + blk) * 1056];
    ((float4*)part)[tid] = a;
    if (tid < 32) {
        float t = 0.f;
        for (int g = 0; g < 8; g++) t += sh[g][tid];
        part[1024 + tid] = t;
    }
}

// ---------------- 2) stats stage 2: channel mask + attention matrix M ----------------
__global__ __launch_bounds__(256) void stats2_k(const float* __restrict__ Wq,
                                                const float* __restrict__ Wk,
                                                const float* __restrict__ fc1,
                                                const float* __restrict__ fc2,
                                                const float* __restrict__ projW,
                                                float* __restrict__ cm_out) {
    int b = blockIdx.x, tid = threadIdx.x;
    __shared__ float scov[1024], savg[32], sQ[1024], sK[1024];
    __shared__ float snq[32], snk[32], sG[256], sA[256], shid[32];
    for (int e = tid; e < 1024; e += 256) {
        float s = 0.f;
        for (int blk = 0; blk < 256; blk++) s += g_part[((size_t)b*256 + blk)*1056 + e];
        scov[e] = s;
    }
    if (tid < 32) {
        float s = 0.f;
        for (int blk = 0; blk < 256; blk++) s += g_part[((size_t)b*256 + blk)*1056 + 1024 + tid];
        savg[tid] = s * (1.f / (float)NPIX);
    }
    __syncthreads();
    // sQ[c][i] = (C_x Wq_c)[i]  (and sK with Wk)
    for (int e = tid; e < 2048; e += 256) {
        int which = e >> 10; int r = e & 1023; int c = r >> 5, i = r & 31;
        const float* Wm = which ? Wk : Wq;
        float s = 0.f;
        for (int j = 0; j < 32; j++) s += scov[i*32 + j] * Wm[c*32 + j];
        if (which) sK[c*32 + i] = s; else sQ[c*32 + i] = s;
    }
    __syncthreads();
    if (tid < 32) { float s = 0.f; for (int i = 0; i < 32; i++) s += Wq[tid*32+i]*sQ[tid*32+i]; snq[tid] = sqrtf(fmaxf(s, 0.f)); }
    else if (tid < 64) { int c = tid-32; float s = 0.f; for (int i = 0; i < 32; i++) s += Wk[c*32+i]*sK[c*32+i]; snk[c] = sqrtf(fmaxf(s, 0.f)); }
    // raw gram restricted to within-head pairs: G[h,d,e] = Wk_{h8+d} . (C_x Wq_{h8+e})
    {
        int h = tid >> 6, d = (tid >> 3) & 7, e = tid & 7;
        int ck = h*8 + d, cq = h*8 + e;
        float s = 0.f;
        for (int i = 0; i < 32; i++) s += Wk[ck*32 + i] * sQ[cq*32 + i];
        sG[tid] = s;
    }
    // channel attention hidden layer
    if (tid >= 64 && tid < 96) {
        int o = tid - 64; float s = 0.f;
        for (int i = 0; i < 32; i++) s += fc1[o*32 + i] * savg[i];
        shid[o] = fmaxf(s, 0.f);
    }
    __syncthreads();
    if (tid < 32) {  // softmax rows of attn
        int h = tid >> 3, d = tid & 7;
        float l[8]; float mx = -1e30f;
        float nk = fmaxf(snk[h*8 + d], 1e-12f);
        for (int e = 0; e < 8; e++) {
            float nq = fmaxf(snq[h*8 + e], 1e-12f);
            l[e] = sG[h*64 + d*8 + e] / (nk * nq);
            mx = fmaxf(mx, l[e]);
        }
        float ssum = 0.f;
        for (int e = 0; e < 8; e++) { l[e] = expf(l[e] - mx); ssum += l[e]; }
        float inv = 1.f / ssum;
        for (int e = 0; e < 8; e++) sA[h*64 + d*8 + e] = l[e] * inv;
    } else if (tid >= 128 && tid < 160) {  // channel mask out
        int c = tid - 128; float s = 0.f;
        for (int i = 0; i < 32; i++) s += fc2[c*32 + i] * shid[i];
        float m = sigmoidf_(s);
        cm_out[b*32 + c] = m;
        g_cmask[b*32 + c] = m;
    }
    __syncthreads();
    // M[o][c'] = sum_d projW[o, h'*8+d] * A[h', d, d']
    for (int e = tid; e < 1024; e += 256) {
        int o = e >> 5, cp = e & 31, hp = cp >> 3, dp = cp & 7;
        float s = 0.f;
        for (int d = 0; d < 8; d++) s += projW[o*32 + hp*8 + d] * sA[hp*64 + d*8 + dp];
        g_M[b*1024 + e] = s;  // e = o*32 + cp
    }
}

// ---------------- 3) spatial mask (folded 49-tap, 1-ch) ----------------
__global__ __launch_bounds__(256) void smask_k(const float* __restrict__ xmsi,
                                               float* __restrict__ sm_out) {
    __shared__ float kc[49*32];
    int tid = threadIdx.x, h = blockIdx.x, b = blockIdx.y;
    for (int e = tid; e < 49*32; e += 256) kc[e] = g_kcomb[e];
    __syncthreads();
    int w = tid;
    float4 a = make_float4(0.f, 0.f, 0.f, 0.f);
    for (int ty = -3; ty <= 3; ty++) {
        int hh = h + ty; if ((unsigned)hh >= (unsigned)HH) continue;
        for (int tx = -3; tx <= 3; tx++) {
            int ww = w + tx; if ((unsigned)ww >= (unsigned)WW) continue;
            const float4* px = (const float4*)(xmsi + (((size_t)b*HH + hh)*WW + ww)*32);
            const float4* kp = (const float4*)(kc + ((ty+3)*7 + (tx+3))*32);
            #pragma unroll
            for (int i4 = 0; i4 < 8; i4++) {
                float4 xv = px[i4], kv = kp[i4];
                a.x += xv.x*kv.x; a.y += xv.y*kv.y; a.z += xv.z*kv.z; a.w += xv.w*kv.w;
            }
        }
    }
    float m = sigmoidf_(a.x + a.y + a.z + a.w);
    size_t pidx = (size_t)b*NPIX + (size_t)h*WW + w;
    g_smask[pidx] = m;
    // reference layout (b,1,w,h)
    sm_out[(size_t)b*NPIX + (size_t)w*HH + h] = m;
}

// ---------------- 4) gated V: (x_fu @ Wv^T) * smask * cmask ----------------
__global__ __launch_bounds__(256) void vgated_k(const float* __restrict__ xfu,
                                                const float* __restrict__ Wv) {
    __shared__ float ws[32*32];  // ws[i*32+o] = Wv[o*32+i]
    __shared__ float cm[32];
    int tid = threadIdx.x, h = blockIdx.x, b = blockIdx.y;
    for (int e = tid; e < 1024; e += 256) {
        int o = e >> 5, i = e & 31;
        ws[i*32 + o] = Wv[e];
    }
    if (tid < 32) cm[tid] = g_cmask[b*32 + tid];
    __syncthreads();
    size_t pidx = (size_t)b*NPIX + (size_t)h*WW + tid;
    const float4* px = (const float4*)(xfu + pidx*32);
    float xr[32];
    #pragma unroll
    for (int i4 = 0; i4 < 8; i4++) {
        float4 v = px[i4];
        xr[i4*4] = v.x; xr[i4*4+1] = v.y; xr[i4*4+2] = v.z; xr[i4*4+3] = v.w;
    }
    float acc[32];
    #pragma unroll
    for (int o = 0; o < 32; o++) acc[o] = 0.f;
    #pragma unroll
    for (int i = 0; i < 32; i++) {
        float x = xr[i];
        const float* wr = &ws[i*32];
        #pragma unroll
        for (int o = 0; o < 32; o++) acc[o] += x * wr[o];
    }
    float sm = g_smask[pidx];
    float4* ob = (float4*)(g_vg + pidx*32);
    #pragma unroll
    for (int i4 = 0; i4 < 8; i4++) {
        float4 r;
        r.x = acc[i4*4]   * sm * cm[i4*4];
        r.y = acc[i4*4+1] * sm * cm[i4*4+1];
        r.z = acc[i4*4+2] * sm * cm[i4*4+2];
        r.w = acc[i4*4+3] * sm * cm[i4*4+3];
        ob[i4] = r;
    }
}

// ---------------- 5) generic 3x3 conv (NHWC, swapped taps), mode-selected buffers ----------------
// mode 0: g_vg -> g_vspec (residual = x_hsi)
// mode 1: g_vspec -> g_tpos (bias, gelu)
__global__ __launch_bounds__(256) void conv3_k(const float* __restrict__ wsrc,
                                               const float* __restrict__ bias,
                                               const float* __restrict__ resid,
                                               int mode, int do_gelu) {
    __shared__ float ws[9*32*32];  // [tap][i][o]
    __shared__ float sb[32];
    int tid = threadIdx.x;
    for (int e = tid; e < 9216; e += 256) {
        int o = e & 31, i = (e >> 5) & 31, t = e >> 10;
        int dh = t / 3, dw = t % 3;
        ws[e] = wsrc[((o*32 + i)*3 + dw)*3 + dh];  // tap-swap for (0,3,2,1) world
    }
    if (tid < 32) sb[tid] = bias ? bias[tid] : 0.f;
    __syncthreads();
    const float* in = (mode == 0) ? g_vg : g_vspec;
    float* outp = (mode == 0) ? g_vspec : g_tpos;
    int w = tid, h = blockIdx.x, b = blockIdx.y;
    float acc[32];
    #pragma unroll
    for (int o = 0; o < 32; o++) acc[o] = sb[o];
    for (int dh = -1; dh <= 1; dh++) {
        int hh = h + dh; if ((unsigned)hh >= (unsigned)HH) continue;
        for (int dw = -1; dw <= 1; dw++) {
            int ww = w + dw; if ((unsigned)ww >= (unsigned)WW) continue;
            const float4* px = (const float4*)(in + (((size_t)b*HH + hh)*WW + ww)*32);
            const float* wt = &ws[((dh+1)*3 + (dw+1)) * 1024];
            #pragma unroll
            for (int i4 = 0; i4 < 8; i4++) {
                float4 xv = px[i4];
                const float* w0 = wt + (i4*4+0)*32;
                const float* w1 = wt + (i4*4+1)*32;
                const float* w2 = wt + (i4*4+2)*32;
                const float* w3 = wt + (i4*4+3)*32;
                #pragma unroll
                for (int o = 0; o < 32; o++)
                    acc[o] += xv.x*w0[o] + xv.y*w1[o] + xv.z*w2[o] + xv.w*w3[o];
            }
        }
    }
    size_t pidx = (((size_t)b*HH + h)*WW + w) * 32;
    if (resid) {
        const float4* r4 = (const float4*)(resid + pidx);
        #pragma unroll
        for (int i4 = 0; i4 < 8; i4++) {
            float4 rv = r4[i4];
            acc[i4*4] += rv.x; acc[i4*4+1] += rv.y; acc[i4*4+2] += rv.z; acc[i4*4+3] += rv.w;
        }
    }
    if (do_gelu) {
        #pragma unroll
        for (int o = 0; o < 32; o++) acc[o] = gelu_exact(acc[o]);
    }
    float4* ob = (float4*)(outp + pidx);
    #pragma unroll
    for (int i4 = 0; i4 < 8; i4++)
        ob[i4] = make_float4(acc[i4*4], acc[i4*4+1], acc[i4*4+2], acc[i4*4+3]);
}

// ---------------- 6) final: gelu(M @ v_spec + pb) + (conv3x3(t_pos) + b2) ----------------
__global__ __launch_bounds__(256) void final_k(const float* __restrict__ w2src,
                                               const float* __restrict__ b2,
                                               const float* __restrict__ projb) {
    __shared__ float ws[9*32*32];
    __shared__ float wm[1024];   // wm[c*32+o] = M[o][c]
    __shared__ float sb2[32], spb[32];
    int tid = threadIdx.x, h = blockIdx.x, b = blockIdx.y;
    for (int e = tid; e < 9216; e += 256) {
        int o = e & 31, i = (e >> 5) & 31, t = e >> 10;
        int dh = t / 3, dw = t % 3;
        ws[e] = w2src[((o*32 + i)*3 + dw)*3 + dh];
    }
    for (int e = tid; e < 1024; e += 256) {
        int c = e >> 5, o = e & 31;
        wm[c*32 + o] = g_M[b*1024 + o*32 + c];
    }
    if (tid < 32) { sb2[tid] = b2[tid]; spb[tid] = projb[tid]; }
    __syncthreads();
    int w = tid;
    size_t pidx = (((size_t)b*HH + h)*WW + w) * 32;
    // out1 = gelu(M @ v_spec + pb); seed acc with out1 + b2, then conv accumulates
    float acc[32];
    {
        float vr[32];
        const float4* pv = (const float4*)(g_vspec + pidx);
        #pragma unroll
        for (int i4 = 0; i4 < 8; i4++) {
            float4 v = pv[i4];
            vr[i4*4] = v.x; vr[i4*4+1] = v.y; vr[i4*4+2] = v.z; vr[i4*4+3] = v.w;
        }
        #pragma unroll
        for (int o = 0; o < 32; o++) acc[o] = spb[o];
        #pragma unroll
        for (int c = 0; c < 32; c++) {
            float x = vr[c];
            const float* wr = &wm[c*32];
            #pragma unroll
            for (int o = 0; o < 32; o++) acc[o] += x * wr[o];
        }
        #pragma unroll
        for (int o = 0; o < 32; o++) acc[o] = gelu_exact(acc[o]) + sb2[o];
    }
    for (int dh = -1; dh <= 1; dh++) {
        int hh = h + dh; if ((unsigned)hh >= (unsigned)HH) continue;
        for (int dw = -1; dw <= 1; dw++) {
            int ww = w + dw; if ((unsigned)ww >= (unsigned)WW) continue;
            const float4* px = (const float4*)(g_tpos + (((size_t)b*HH + hh)*WW + ww)*32);
            const float* wt = &ws[((dh+1)*3 + (dw+1)) * 1024];
            #pragma unroll
            for (int i4 = 0; i4 < 8; i4++) {
                float4 xv = px[i4];
                const float* w0 = wt + (i4*4+0)*32;
                const float* w1 = wt + (i4*4+1)*32;
                const float* w2 = wt + (i4*4+2)*32;
                const float* w3 = wt + (i4*4+3)*32;
                #pragma unroll
                for (int o = 0; o < 32; o++)
                    acc[o] += xv.x*w0[o] + xv.y*w1[o] + xv.z*w2[o] + xv.w*w3[o];
            }
        }
    }
    float4* ob = (float4*)(g_outn + pidx);
    #pragma unroll
    for (int i4 = 0; i4 < 8; i4++)
        ob[i4] = make_float4(acc[i4*4], acc[i4*4+1], acc[i4*4+2], acc[i4*4+3]);
}

// ---------------- 7) transpose NHWC -> (b,c,w,h) ----------------
__global__ void transpose_k(float* __restrict__ out0) {
    __shared__ float tile[32][33];
    int b = blockIdx.z, w = blockIdx.y, h0 = blockIdx.x * 32;
    int tx = threadIdx.x, ty = threadIdx.y;
    tile[ty][tx] = g_outn[(((size_t)b*HH + (h0 + ty))*WW + w)*32 + tx];
    __syncthreads();
    out0[(((size_t)b*CC + ty)*WW + w)*HH + h0 + tx] = tile[tx][ty];
}

// ---------------- launch ----------------
extern "C" void kernel_launch(void* const* d_in, const int* in_sizes, int n_in,
                              void* d_out, int out_size) {
    const float* x_fu   = (const float*)d_in[0];
    const float* x_msi  = (const float*)d_in[1];
    const float* x_hsi  = (const float*)d_in[2];
    const float* Wq     = (const float*)d_in[3];
    const float* Wk     = (const float*)d_in[4];
    const float* Wv     = (const float*)d_in[5];
    const float* proj_W = (const float*)d_in[6];
    const float* proj_b = (const float*)d_in[7];
    const float* pos1_W = (const float*)d_in[8];
    const float* pos1_b = (const float*)d_in[9];
    const float* pos2_W = (const float*)d_in[10];
    const float* pos2_b = (const float*)d_in[11];
    const float* ca_fc1 = (const float*)d_in[12];
    const float* ca_fc2 = (const float*)d_in[13];
    const float* sa_c1a = (const float*)d_in[14];
    const float* sa_c1b = (const float*)d_in[15];
    const float* sa_c2a = (const float*)d_in[16];
    const float* sa_c2b = (const float*)d_in[17];
    const float* sa_c3  = (const float*)d_in[18];
    const float* attn_W = (const float*)d_in[19];

    float* out0   = (float*)d_out;          // (b,c,w,h): 8388608
    float* cm_out = out0 + IMG_ELEMS;       // (b,c,1,1): 128
    float* sm_out = cm_out + BB*CC;         // (b,1,w,h): 262144

    dim3 g(HH, BB);
    prep_k  <<<1, 256>>>(sa_c1a, sa_c1b, sa_c2a, sa_c2b, sa_c3);
    stats1_k<<<dim3(256, BB), 256>>>(x_fu, x_hsi);
    stats2_k<<<BB, 256>>>(Wq, Wk, ca_fc1, ca_fc2, proj_W, cm_out);
    smask_k <<<g, 256>>>(x_msi, sm_out);
    vgated_k<<<g, 256>>>(x_fu, Wv);
    conv3_k <<<g, 256>>>(attn_W, (const float*)nullptr, x_hsi, 0, 0);  // v_spec
    conv3_k <<<g, 256>>>(pos1_W, pos1_b, (const float*)nullptr, 1, 1); // t_pos
    final_k <<<g, 256>>>(pos2_W, pos2_b, proj_b);
    transpose_k<<<dim3(HH/32, WW, BB), dim3(32, 32)>>>(out0);
}

// round 3
// speedup vs baseline: 1.4362x; 1.4362x over previous
#include <cuda_runtime.h>
#include <math.h>

// ---------------- problem constants ----------------
#define BB 4
#define HH 256
#define WW 256
#define CC 32
#define NPIX (HH*WW)            // 65536
#define IMG_ELEMS (BB*NPIX*CC)  // 8388608

typedef unsigned long long ull;

// ---------------- device scratch ----------------
__device__ float g_part[BB*256*1056];
__device__ float g_M[BB*1024];
__device__ float g_cmask[BB*CC];
__device__ float g_smask[BB*NPIX];
__device__ float g_kcomb[49*32];
__device__ float g_vg[IMG_ELEMS];
__device__ float g_vspec[IMG_ELEMS];
__device__ float g_tpos[IMG_ELEMS];
__device__ float g_outn[IMG_ELEMS];

__device__ __forceinline__ float gelu_exact(float x) {
    return 0.5f * x * (1.0f + erff(x * 0.70710678118654752f));
}
__device__ __forceinline__ float sigmoidf_(float x) {
    return 1.0f / (1.0f + expf(-x));
}

// ---------------- packed f32x2 helpers ----------------
__device__ __forceinline__ void fma2(ull& c, ull a, ull b) {
    asm("fma.rn.f32x2 %0, %1, %2, %0;" : "+l"(c) : "l"(a), "l"(b));
}
__device__ __forceinline__ ull pk2(float x) {          // {x, x}
    ull r; asm("mov.b64 %0, {%1, %1};" : "=l"(r) : "f"(x)); return r;
}
__device__ __forceinline__ ull pkpair(float lo, float hi) {
    ull r; asm("mov.b64 %0, {%1, %2};" : "=l"(r) : "f"(lo), "f"(hi)); return r;
}
__device__ __forceinline__ float2 upk(ull v) {
    float2 f; asm("mov.b64 {%0, %1}, %2;" : "=f"(f.x), "=f"(f.y) : "l"(v)); return f;
}

// ---------------- 0) fold spatial-attention kernels ----------------
__global__ void prep_k(const float* __restrict__ c1a, const float* __restrict__ c1b,
                       const float* __restrict__ c2a, const float* __restrict__ c2b,
                       const float* __restrict__ c3) {
    int tid = threadIdx.x;
    float w3 = c3[0], w7 = c3[1];
    for (int e = tid; e < 49*32; e += 256) {
        int t = e >> 5, i = e & 31;
        int ty = t / 7 - 3, tx = t % 7 - 3;
        float s = 0.f;
        for (int o = 0; o < 32; o++)
            s += c2b[o] * c2a[((o*32 + i)*7 + (tx+3))*7 + (ty+3)];
        s *= w7;
        if (tx >= -1 && tx <= 1 && ty >= -1 && ty <= 1) {
            float s1 = 0.f;
            for (int o = 0; o < 32; o++)
                s1 += c1b[o] * c1a[((o*32 + i)*3 + (tx+1))*3 + (ty+1)];
            s += w3 * s1;
        }
        g_kcomb[e] = s;
    }
}

// ---------------- 1) stats stage 1 ----------------
__global__ __launch_bounds__(256) void stats1_k(const float* __restrict__ xfu,
                                                const float* __restrict__ xhsi) {
    __shared__ float sx[256*32];
    __shared__ float sh[8][32];
    int b = blockIdx.y, blk = blockIdx.x, tid = threadIdx.x;
    size_t base = ((size_t)b*NPIX + (size_t)blk*256) * 32;
    for (int k = 0; k < 32; k++) sx[k*256 + tid] = xfu[base + (size_t)k*256 + tid];
    {
        int c = tid & 31, grp = tid >> 5;
        float s = 0.f;
        for (int p = grp; p < 256; p += 8) s += xhsi[base + (size_t)p*32 + c];
        sh[grp][c] = s;
    }
    __syncthreads();
    int e0 = tid * 4;
    int i = e0 >> 5, j0 = e0 & 31;
    float4 a = make_float4(0.f, 0.f, 0.f, 0.f);
    const float4* sx4 = (const float4*)sx;
    for (int p = 0; p < 256; p++) {
        float xi = sx[p*32 + i];
        float4 xj = sx4[p*8 + (j0 >> 2)];
        a.x += xi * xj.x; a.y += xi * xj.y; a.z += xi * xj.z; a.w += xi * xj.w;
    }
    float* part = &g_part[((size_t)b*256 + blk) * 1056];
    ((float4*)part)[tid] = a;
    if (tid < 32) {
        float t = 0.f;
        for (int g = 0; g < 8; g++) t += sh[g][tid];
        part[1024 + tid] = t;
    }
}

// ---------------- 2) stats stage 2 ----------------
__global__ __launch_bounds__(256) void stats2_k(const float* __restrict__ Wq,
                                                const float* __restrict__ Wk,
                                                const float* __restrict__ fc1,
                                                const float* __restrict__ fc2,
                                                const float* __restrict__ projW,
                                                float* __restrict__ cm_out) {
    int b = blockIdx.x, tid = threadIdx.x;
    __shared__ float scov[1024], savg[32], sQ[1024], sK[1024];
    __shared__ float snq[32], snk[32], sG[256], sA[256], shid[32];
    for (int e = tid; e < 1024; e += 256) {
        float s = 0.f;
        for (int blk = 0; blk < 256; blk++) s += g_part[((size_t)b*256 + blk)*1056 + e];
        scov[e] = s;
    }
    if (tid < 32) {
        float s = 0.f;
        for (int blk = 0; blk < 256; blk++) s += g_part[((size_t)b*256 + blk)*1056 + 1024 + tid];
        savg[tid] = s * (1.f / (float)NPIX);
    }
    __syncthreads();
    for (int e = tid; e < 2048; e += 256) {
        int which = e >> 10; int r = e & 1023; int c = r >> 5, i = r & 31;
        const float* Wm = which ? Wk : Wq;
        float s = 0.f;
        for (int j = 0; j < 32; j++) s += scov[i*32 + j] * Wm[c*32 + j];
        if (which) sK[c*32 + i] = s; else sQ[c*32 + i] = s;
    }
    __syncthreads();
    if (tid < 32) { float s = 0.f; for (int i = 0; i < 32; i++) s += Wq[tid*32+i]*sQ[tid*32+i]; snq[tid] = sqrtf(fmaxf(s, 0.f)); }
    else if (tid < 64) { int c = tid-32; float s = 0.f; for (int i = 0; i < 32; i++) s += Wk[c*32+i]*sK[c*32+i]; snk[c] = sqrtf(fmaxf(s, 0.f)); }
    {
        int h = tid >> 6, d = (tid >> 3) & 7, e = tid & 7;
        int ck = h*8 + d, cq = h*8 + e;
        float s = 0.f;
        for (int i = 0; i < 32; i++) s += Wk[ck*32 + i] * sQ[cq*32 + i];
        sG[tid] = s;
    }
    if (tid >= 64 && tid < 96) {
        int o = tid - 64; float s = 0.f;
        for (int i = 0; i < 32; i++) s += fc1[o*32 + i] * savg[i];
        shid[o] = fmaxf(s, 0.f);
    }
    __syncthreads();
    if (tid < 32) {
        int h = tid >> 3, d = tid & 7;
        float l[8]; float mx = -1e30f;
        float nk = fmaxf(snk[h*8 + d], 1e-12f);
        for (int e = 0; e < 8; e++) {
            float nq = fmaxf(snq[h*8 + e], 1e-12f);
            l[e] = sG[h*64 + d*8 + e] / (nk * nq);
            mx = fmaxf(mx, l[e]);
        }
        float ssum = 0.f;
        for (int e = 0; e < 8; e++) { l[e] = expf(l[e] - mx); ssum += l[e]; }
        float inv = 1.f / ssum;
        for (int e = 0; e < 8; e++) sA[h*64 + d*8 + e] = l[e] * inv;
    } else if (tid >= 128 && tid < 160) {
        int c = tid - 128; float s = 0.f;
        for (int i = 0; i < 32; i++) s += fc2[c*32 + i] * shid[i];
        float m = sigmoidf_(s);
        cm_out[b*32 + c] = m;
        g_cmask[b*32 + c] = m;
    }
    __syncthreads();
    for (int e = tid; e < 1024; e += 256) {
        int o = e >> 5, cp = e & 31, hp = cp >> 3, dp = cp & 7;
        float s = 0.f;
        for (int d = 0; d < 8; d++) s += projW[o*32 + hp*8 + d] * sA[hp*64 + d*8 + dp];
        g_M[b*1024 + e] = s;
    }
}

// ---------------- 3) spatial mask: smem-tiled 16x16, padded stride 36 ----------------
#define SM_TILE 16
#define SM_IN   22            // 16 + 6 halo
#define SM_STR  36            // padded channel stride (bank-conflict-free LDS.128)
#define SMASK_XF (SM_IN*SM_IN*SM_STR)   // 17424 floats
#define SMASK_SMEM ((SMASK_XF + 49*32) * 4)

__global__ __launch_bounds__(256) void smask_k(const float* __restrict__ xmsi,
                                               float* __restrict__ sm_out) {
    extern __shared__ float dyn[];
    float* sx = dyn;
    float* kc = dyn + SMASK_XF;
    int tid = threadIdx.x, bx = blockIdx.x, by = blockIdx.y, b = blockIdx.z;
    for (int e = tid; e < 49*32; e += 256) kc[e] = g_kcomb[e];
    // load 22x22 halo tile (zero-padded)
    for (int slot = tid; slot < SM_IN*SM_IN; slot += 256) {
        int r = slot / SM_IN, c = slot % SM_IN;
        int gh = by*SM_TILE + r - 3, gw = bx*SM_TILE + c - 3;
        float4* dst = (float4*)&sx[slot*SM_STR];
        if ((unsigned)gh < (unsigned)HH && (unsigned)gw < (unsigned)WW) {
            const float4* src = (const float4*)(xmsi + (((size_t)b*HH + gh)*WW + gw)*32);
            #pragma unroll
            for (int i4 = 0; i4 < 8; i4++) dst[i4] = src[i4];
        } else {
            #pragma unroll
            for (int i4 = 0; i4 < 8; i4++) dst[i4] = make_float4(0.f,0.f,0.f,0.f);
        }
    }
    __syncthreads();
    int ty = tid >> 4, tx = tid & 15;
    ull acc = 0ull;
    #pragma unroll 1
    for (int dy = 0; dy < 7; dy++) {
        #pragma unroll 1
        for (int dx = 0; dx < 7; dx++) {
            const ulonglong2* xp = (const ulonglong2*)&sx[((ty+dy)*SM_IN + tx+dx)*SM_STR];
            const ulonglong2* kp = (const ulonglong2*)&kc[(dy*7 + dx)*32];
            #pragma unroll
            for (int i4 = 0; i4 < 8; i4++) {
                ulonglong2 xv = xp[i4], kv = kp[i4];
                fma2(acc, xv.x, kv.x);
                fma2(acc, xv.y, kv.y);
            }
        }
    }
    float2 f = upk(acc);
    float m = sigmoidf_(f.x + f.y);
    int h = by*SM_TILE + ty, w = bx*SM_TILE + tx;
    g_smask[(size_t)b*NPIX + (size_t)h*WW + w] = m;
    sm_out[(size_t)b*NPIX + (size_t)w*HH + h] = m;
}

// ---------------- 4) gated V (f32x2 over output-channel pairs) ----------------
__global__ __launch_bounds__(256) void vgated_k(const float* __restrict__ xfu,
                                                const float* __restrict__ Wv) {
    __shared__ float ws[32*32];  // ws[i*32+o] = Wv[o*32+i]
    __shared__ float cm[32];
    int tid = threadIdx.x, h = blockIdx.x, b = blockIdx.y;
    for (int e = tid; e < 1024; e += 256) {
        int o = e >> 5, i = e & 31;
        ws[i*32 + o] = Wv[e];
    }
    if (tid < 32) cm[tid] = g_cmask[b*32 + tid];
    __syncthreads();
    size_t pidx = (size_t)b*NPIX + (size_t)h*WW + tid;
    const float4* px = (const float4*)(xfu + pidx*32);
    ull acc[16];
    #pragma unroll
    for (int q = 0; q < 16; q++) acc[q] = 0ull;
    #pragma unroll
    for (int i4 = 0; i4 < 8; i4++) {
        float4 v = px[i4];
        #pragma unroll
        for (int i = 0; i < 4; i++) {
            ull a = pk2((&v.x)[i]);
            const ulonglong2* wr = (const ulonglong2*)&ws[(i4*4 + i)*32];
            #pragma unroll
            for (int q = 0; q < 8; q++) {
                ulonglong2 wv = wr[q];
                fma2(acc[2*q], a, wv.x);
                fma2(acc[2*q+1], a, wv.y);
            }
        }
    }
    float sm = g_smask[pidx];
    float4* ob = (float4*)(g_vg + pidx*32);
    #pragma unroll
    for (int i4 = 0; i4 < 8; i4++) {
        float2 p0 = upk(acc[i4*2]), p1 = upk(acc[i4*2+1]);
        float4 r;
        r.x = p0.x * sm * cm[i4*4];
        r.y = p0.y * sm * cm[i4*4+1];
        r.z = p1.x * sm * cm[i4*4+2];
        r.w = p1.y * sm * cm[i4*4+3];
        ob[i4] = r;
    }
}

// ---------------- 5) 3x3 conv, 2 pixels/thread, f32x2 o-pair packed ----------------
// mode 0: g_vg -> g_vspec (residual = x_hsi); mode 1: g_vspec -> g_tpos (bias+gelu)
__global__ __launch_bounds__(128) void conv3_k(const float* __restrict__ wsrc,
                                               const float* __restrict__ bias,
                                               const float* __restrict__ resid,
                                               int mode, int do_gelu) {
    __shared__ float ws[9*32*32];  // [tap][i][o], o contiguous
    __shared__ float sb[32];
    int tid = threadIdx.x;
    for (int e = tid; e < 9216; e += 128) {
        int o = e & 31, i = (e >> 5) & 31, t = e >> 10;
        int dh = t / 3, dw = t % 3;
        ws[e] = wsrc[((o*32 + i)*3 + dw)*3 + dh];  // tap-swap for (0,3,2,1) world
    }
    if (tid < 32) sb[tid] = bias ? bias[tid] : 0.f;
    __syncthreads();
    const float* in = (mode == 0) ? g_vg : g_vspec;
    float* outp = (mode == 0) ? g_vspec : g_tpos;
    int h = blockIdx.x, b = blockIdx.y, w0 = tid * 2;
    ull acc0[16], acc1[16];
    #pragma unroll
    for (int q = 0; q < 16; q++) {
        ull bv = pkpair(sb[2*q], sb[2*q+1]);
        acc0[q] = bv; acc1[q] = bv;
    }
    #pragma unroll 1
    for (int dh = -1; dh <= 1; dh++) {
        int hh = h + dh; if ((unsigned)hh >= (unsigned)HH) continue;
        #pragma unroll 1
        for (int dw = -1; dw <= 1; dw++) {
            int ww0 = w0 + dw, ww1 = w0 + 1 + dw;
            bool v0 = (unsigned)ww0 < (unsigned)WW, v1 = (unsigned)ww1 < (unsigned)WW;
            const float4* p0 = (const float4*)(in + (((size_t)b*HH + hh)*WW + ww0)*32);
            const float4* p1 = (const float4*)(in + (((size_t)b*HH + hh)*WW + ww1)*32);
            const float* wt = &ws[((dh+1)*3 + (dw+1)) * 1024];
            #pragma unroll
            for (int i4 = 0; i4 < 8; i4++) {
                float4 x0 = v0 ? p0[i4] : make_float4(0.f,0.f,0.f,0.f);
                float4 x1 = v1 ? p1[i4] : make_float4(0.f,0.f,0.f,0.f);
                #pragma unroll
                for (int i = 0; i < 4; i++) {
                    ull a0 = pk2((&x0.x)[i]);
                    ull a1 = pk2((&x1.x)[i]);
                    const ulonglong2* wr = (const ulonglong2*)(wt + (i4*4 + i)*32);
                    #pragma unroll
                    for (int q = 0; q < 8; q++) {
                        ulonglong2 wv = wr[q];
                        fma2(acc0[2*q],   a0, wv.x);
                        fma2(acc0[2*q+1], a0, wv.y);
                        fma2(acc1[2*q],   a1, wv.x);
                        fma2(acc1[2*q+1], a1, wv.y);
                    }
                }
            }
        }
    }
    size_t pidx0 = (((size_t)b*HH + h)*WW + w0) * 32;
    #pragma unroll 1
    for (int p = 0; p < 2; p++) {
        ull* acc = p ? acc1 : acc0;
        size_t pidx = pidx0 + (size_t)p*32;
        float out[32];
        #pragma unroll
        for (int q = 0; q < 16; q++) {
            float2 f = upk(acc[q]);
            out[2*q] = f.x; out[2*q+1] = f.y;
        }
        if (resid) {
            const float4* r4 = (const float4*)(resid + pidx);
            #pragma unroll
            for (int i4 = 0; i4 < 8; i4++) {
                float4 rv = r4[i4];
                out[i4*4] += rv.x; out[i4*4+1] += rv.y; out[i4*4+2] += rv.z; out[i4*4+3] += rv.w;
            }
        }
        if (do_gelu) {
            #pragma unroll
            for (int o = 0; o < 32; o++) out[o] = gelu_exact(out[o]);
        }
        float4* ob = (float4*)(outp + pidx);
        #pragma unroll
        for (int i4 = 0; i4 < 8; i4++)
            ob[i4] = make_float4(out[i4*4], out[i4*4+1], out[i4*4+2], out[i4*4+3]);
    }
}

// ---------------- 6) final: gelu(M @ v_spec + pb) + conv3x3(t_pos) + b2 ----------------
__global__ __launch_bounds__(256) void final_k(const float* __restrict__ w2src,
                                               const float* __restrict__ b2,
                                               const float* __restrict__ projb) {
    __shared__ float ws[9*32*32];
    __shared__ float wm[1024];   // wm[c*32+o] = M[o][c]
    __shared__ float sb2[32], spb[32];
    int tid = threadIdx.x, h = blockIdx.x, b = blockIdx.y;
    for (int e = tid; e < 9216; e += 256) {
        int o = e & 31, i = (e >> 5) & 31, t = e >> 10;
        int dh = t / 3, dw = t % 3;
        ws[e] = w2src[((o*32 + i)*3 + dw)*3 + dh];
    }
    for (int e = tid; e < 1024; e += 256) {
        int c = e >> 5, o = e & 31;
        wm[c*32 + o] = g_M[b*1024 + o*32 + c];
    }
    if (tid < 32) { sb2[tid] = b2[tid]; spb[tid] = projb[tid]; }
    __syncthreads();
    int w = tid;
    size_t pidx = (((size_t)b*HH + h)*WW + w) * 32;
    ull acc[16];
    #pragma unroll
    for (int q = 0; q < 16; q++) acc[q] = pkpair(spb[2*q], spb[2*q+1]);
    // matvec M @ v_spec
    {
        const float4* pv = (const float4*)(g_vspec + pidx);
        #pragma unroll
        for (int i4 = 0; i4 < 8; i4++) {
            float4 v = pv[i4];
            #pragma unroll
            for (int i = 0; i < 4; i++) {
                ull a = pk2((&v.x)[i]);
                const ulonglong2* wr = (const ulonglong2*)&wm[(i4*4 + i)*32];
                #pragma unroll
                for (int q = 0; q < 8; q++) {
                    ulonglong2 wv = wr[q];
                    fma2(acc[2*q],   a, wv.x);
                    fma2(acc[2*q+1], a, wv.y);
                }
            }
        }
    }
    #pragma unroll
    for (int q = 0; q < 16; q++) {
        float2 f = upk(acc[q]);
        acc[q] = pkpair(gelu_exact(f.x) + sb2[2*q], gelu_exact(f.y) + sb2[2*q+1]);
    }
    // conv3x3 on g_tpos accumulated into acc
    #pragma unroll 1
    for (int dh = -1; dh <= 1; dh++) {
        int hh = h + dh; if ((unsigned)hh >= (unsigned)HH) continue;
        #pragma unroll 1
        for (int dw = -1; dw <= 1; dw++) {
            int ww = w + dw; if ((unsigned)ww >= (unsigned)WW) continue;
            const float4* px = (const float4*)(g_tpos + (((size_t)b*HH + hh)*WW + ww)*32);
            const float* wt = &ws[((dh+1)*3 + (dw+1)) * 1024];
            #pragma unroll
            for (int i4 = 0; i4 < 8; i4++) {
                float4 xv = px[i4];
                #pragma unroll
                for (int i = 0; i < 4; i++) {
                    ull a = pk2((&xv.x)[i]);
                    const ulonglong2* wr = (const ulonglong2*)(wt + (i4*4 + i)*32);
                    #pragma unroll
                    for (int q = 0; q < 8; q++) {
                        ulonglong2 wv = wr[q];
                        fma2(acc[2*q],   a, wv.x);
                        fma2(acc[2*q+1], a, wv.y);
                    }
                }
            }
        }
    }
    float4* ob = (float4*)(g_outn + pidx);
    #pragma unroll
    for (int q = 0; q < 8; q++) {
        float2 f0 = upk(acc[2*q]), f1 = upk(acc[2*q+1]);
        ob[q] = make_float4(f0.x, f0.y, f1.x, f1.y);
    }
}

// ---------------- 7) transpose NHWC -> (b,c,w,h) ----------------
__global__ void transpose_k(float* __restrict__ out0) {
    __shared__ float tile[32][33];
    int b = blockIdx.z, w = blockIdx.y, h0 = blockIdx.x * 32;
    int tx = threadIdx.x, ty = threadIdx.y;
    tile[ty][tx] = g_outn[(((size_t)b*HH + (h0 + ty))*WW + w)*32 + tx];
    __syncthreads();
    out0[(((size_t)b*CC + ty)*WW + w)*HH + h0 + tx] = tile[tx][ty];
}

// ---------------- launch ----------------
extern "C" void kernel_launch(void* const* d_in, const int* in_sizes, int n_in,
                              void* d_out, int out_size) {
    const float* x_fu   = (const float*)d_in[0];
    const float* x_msi  = (const float*)d_in[1];
    const float* x_hsi  = (const float*)d_in[2];
    const float* Wq     = (const float*)d_in[3];
    const float* Wk     = (const float*)d_in[4];
    const float* Wv     = (const float*)d_in[5];
    const float* proj_W = (const float*)d_in[6];
    const float* proj_b = (const float*)d_in[7];
    const float* pos1_W = (const float*)d_in[8];
    const float* pos1_b = (const float*)d_in[9];
    const float* pos2_W = (const float*)d_in[10];
    const float* pos2_b = (const float*)d_in[11];
    const float* ca_fc1 = (const float*)d_in[12];
    const float* ca_fc2 = (const float*)d_in[13];
    const float* sa_c1a = (const float*)d_in[14];
    const float* sa_c1b = (const float*)d_in[15];
    const float* sa_c2a = (const float*)d_in[16];
    const float* sa_c2b = (const float*)d_in[17];
    const float* sa_c3  = (const float*)d_in[18];
    const float* attn_W = (const float*)d_in[19];

    float* out0   = (float*)d_out;
    float* cm_out = out0 + IMG_ELEMS;
    float* sm_out = cm_out + BB*CC;

    cudaFuncSetAttribute(smask_k, cudaFuncAttributeMaxDynamicSharedMemorySize, SMASK_SMEM);

    dim3 g(HH, BB);
    prep_k  <<<1, 256>>>(sa_c1a, sa_c1b, sa_c2a, sa_c2b, sa_c3);
    stats1_k<<<dim3(256, BB), 256>>>(x_fu, x_hsi);
    stats2_k<<<BB, 256>>>(Wq, Wk, ca_fc1, ca_fc2, proj_W, cm_out);
    smask_k <<<dim3(WW/SM_TILE, HH/SM_TILE, BB), 256, SMASK_SMEM>>>(x_msi, sm_out);
    vgated_k<<<g, 256>>>(x_fu, Wv);
    conv3_k <<<g, 128>>>(attn_W, (const float*)nullptr, x_hsi, 0, 0);  // v_spec
    conv3_k <<<g, 128>>>(pos1_W, pos1_b, (const float*)nullptr, 1, 1); // t_pos
    final_k <<<g, 256>>>(pos2_W, pos2_b, proj_b);
    transpose_k<<<dim3(HH/32, WW, BB), dim3(32, 32)>>>(out0);
}